// round 1
// baseline (speedup 1.0000x reference)
#include <cuda_runtime.h>
#include <cuda_bf16.h>
#include <math.h>

// BERTEmbedding: out[row, 0:256]   = x[row,0:10] @ W[256,10]^T + b
//                out[row, 256:512] = sinusoidal PE at pos = doy[row]
// rows = B*S = 131072, output = 268 MB fp32 -> HBM-write-bound.
//
// Thread layout: blockDim = 256 = 2 row-groups of 128 threads.
//   In each group: lanes 0..63  (warps 0-1): obs half, 4 output cols each (float4)
//                  lanes 64..127(warps 2-3): PE half,  4 output cols each (float4)
// W rows for a thread's fixed 4 columns live in registers (loaded once per block,
// amortized over the grid-stride loop). PE computed inline (no table, no gather).

#define TPB 256
#define NBLK 1184  // 148 SMs * 8; grid-stride loop handles the rest

__global__ void __launch_bounds__(TPB) bert_embed_kernel(
    const float* __restrict__ x,      // [rows, 10]
    const int*   __restrict__ doy,    // [rows]
    const float* __restrict__ W,      // [256, 10] row-major
    const float* __restrict__ bias,   // [256]
    float*       __restrict__ out,    // [rows, 512]
    int nrows)
{
    const int t     = threadIdx.x;
    const int group = t >> 7;        // 0 or 1: which row this half-block handles
    const int l     = t & 127;       // lane within the 128-thread row-group
    const bool is_obs = (l < 64);

    // ---- per-thread constant setup (once per block) ----
    float wreg[40];
    float breg[4];
    float div0 = 0.f, div1 = 0.f;

    if (is_obs) {
        const int c0 = l * 4;        // first of this thread's 4 output columns
        #pragma unroll
        for (int j = 0; j < 4; ++j) {
            breg[j] = bias[c0 + j];
            #pragma unroll
            for (int f = 0; f < 10; ++f)
                wreg[j * 10 + f] = W[(c0 + j) * 10 + f];
        }
    } else {
        // PE cols p = 4*(l-64) .. +3.  pe[2i]=sin(pos*div[i]), pe[2i+1]=cos(...)
        // div[i] = exp(2i * (-ln(10000)/256)), this thread owns i0 = 2*(l-64), i1 = i0+1
        const int   i0 = (l - 64) * 2;
        const float k  = -9.210340371976184f / 256.0f;  // -ln(10000)/D
        div0 = expf(k * (float)(2 * i0));
        div1 = expf(k * (float)(2 * i0 + 2));
    }

    const int stride = gridDim.x * 2;
    for (int row = blockIdx.x * 2 + group; row < nrows; row += stride) {
        float4 v;
        if (is_obs) {
            // input row: 10 floats, 8B-aligned (row*40 bytes) -> 5x float2
            const float2* xp = reinterpret_cast<const float2*>(x + (size_t)row * 10);
            float xv[10];
            #pragma unroll
            for (int k2 = 0; k2 < 5; ++k2) {
                float2 p = __ldg(xp + k2);
                xv[2 * k2]     = p.x;
                xv[2 * k2 + 1] = p.y;
            }
            #pragma unroll
            for (int j = 0; j < 4; ++j) {
                float acc = breg[j];
                #pragma unroll
                for (int f = 0; f < 10; ++f)
                    acc = fmaf(xv[f], wreg[j * 10 + f], acc);
                (&v.x)[j] = acc;
            }
            *reinterpret_cast<float4*>(out + (size_t)row * 512 + l * 4) = v;
        } else {
            const float pos = (float)__ldg(doy + row);
            float s0, c0, s1, c1;
            sincosf(pos * div0, &s0, &c0);
            sincosf(pos * div1, &s1, &c1);
            v = make_float4(s0, c0, s1, c1);
            *reinterpret_cast<float4*>(out + (size_t)row * 512 + 256 + (l - 64) * 4) = v;
        }
    }
}

extern "C" void kernel_launch(void* const* d_in, const int* in_sizes, int n_in,
                              void* d_out, int out_size) {
    const float* x    = (const float*)d_in[0];   // input_sequence [B,S,10]
    const int*   doy  = (const int*)  d_in[1];   // doy_sequence   [B,S]
    const float* W    = (const float*)d_in[2];   // W [256,10]
    const float* bias = (const float*)d_in[3];   // b [256]
    float*       out  = (float*)d_out;           // [B,S,512]

    const int nrows = in_sizes[1];               // B*S from doy element count

    bert_embed_kernel<<<NBLK, TPB>>>(x, doy, W, bias, out, nrows);
}

// round 2
// speedup vs baseline: 1.3900x; 1.3900x over previous
#include <cuda_runtime.h>
#include <cuda_bf16.h>
#include <math.h>

// BERTEmbedding: out[row, 0:256]   = x[row,0:10] @ W[256,10]^T + b
//                out[row, 256:512] = sinusoidal PE at pos = doy[row]
// rows = B*S = 131072; output 268 MB fp32 -> HBM-write-bound target.
//
// R2 changes vs R1:
//  - PE via precomputed __device__ table (366x256 = 375 KB, L2-resident);
//    removes 16.8M runtime sincosf calls (was fma/alu latency bound).
//  - W cached in SMEM transposed (f-major, float4 conflict-free) instead of
//    40 registers/thread: regs 77 -> ~35, occupancy 3 -> 6+ blocks/SM.

#define MAX_LEN 366
#define D_HALF  256
#define TPB     256
#define NBLK    1480   // grid-stride; ~44 row-pairs per block

__device__ float g_pe[MAX_LEN * D_HALF];  // [pos][col]

// Build PE table: 366 blocks x 128 threads; thread i -> cols 2i, 2i+1.
__global__ void build_pe_kernel() {
    const int pos = blockIdx.x;
    const int i   = threadIdx.x;                 // 0..127
    const float k = -9.210340371976184f / 256.0f; // -ln(10000)/D
    const float div = expf(k * (float)(2 * i));
    float s, c;
    sincosf((float)pos * div, &s, &c);
    g_pe[pos * D_HALF + 2 * i]     = s;
    g_pe[pos * D_HALF + 2 * i + 1] = c;
}

__global__ void __launch_bounds__(TPB) bert_embed_kernel(
    const float* __restrict__ x,      // [rows, 10]
    const int*   __restrict__ doy,    // [rows]
    const float* __restrict__ W,      // [256, 10] row-major
    const float* __restrict__ bias,   // [256]
    float*       __restrict__ out,    // [rows, 512]
    int nrows)
{
    // smem: W transposed, f-major: wt[f][c] = W[c][f]; float4-readable.
    __shared__ float s_wt[10 * D_HALF];   // 10 KB
    __shared__ float s_b[D_HALF];         // 1 KB

    const int t = threadIdx.x;

    // Cooperative fill (strided; once per block).
    for (int idx = t; idx < 10 * D_HALF; idx += TPB) {
        const int f = idx >> 8;           // idx / 256
        const int c = idx & 255;          // idx % 256
        s_wt[idx] = W[c * 10 + f];
    }
    for (int idx = t; idx < D_HALF; idx += TPB)
        s_b[idx] = bias[idx];
    __syncthreads();

    const int group   = t >> 7;           // 0/1: which row of the pair
    const int l       = t & 127;          // lane within 128-thread row-group
    const bool is_obs = (l < 64);

    const float4* wt4 = reinterpret_cast<const float4*>(s_wt);  // [10][64]

    // Obs threads: cache bias float4 in regs (loop-invariant).
    float4 bv = make_float4(0.f, 0.f, 0.f, 0.f);
    if (is_obs) bv = reinterpret_cast<const float4*>(s_b)[l];

    const int stride = gridDim.x * 2;
    for (int row = blockIdx.x * 2 + group; row < nrows; row += stride) {
        if (is_obs) {
            // x row: 10 floats, 8B-aligned -> 5x float2 (broadcast across group)
            const float2* xp = reinterpret_cast<const float2*>(x + (size_t)row * 10);
            float xv[10];
            #pragma unroll
            for (int k2 = 0; k2 < 5; ++k2) {
                float2 p = __ldg(xp + k2);
                xv[2 * k2]     = p.x;
                xv[2 * k2 + 1] = p.y;
            }
            float4 acc = bv;
            #pragma unroll
            for (int f = 0; f < 10; ++f) {
                float4 w = wt4[f * 64 + l];     // conflict-free LDS.128
                acc.x = fmaf(xv[f], w.x, acc.x);
                acc.y = fmaf(xv[f], w.y, acc.y);
                acc.z = fmaf(xv[f], w.z, acc.z);
                acc.w = fmaf(xv[f], w.w, acc.w);
            }
            *reinterpret_cast<float4*>(out + (size_t)row * 512 + l * 4) = acc;
        } else {
            const int p = __ldg(doy + row);
            const float4 v = *reinterpret_cast<const float4*>(
                g_pe + p * D_HALF + (l - 64) * 4);
            *reinterpret_cast<float4*>(out + (size_t)row * 512 + 256 + (l - 64) * 4) = v;
        }
    }
}

extern "C" void kernel_launch(void* const* d_in, const int* in_sizes, int n_in,
                              void* d_out, int out_size) {
    const float* x    = (const float*)d_in[0];   // input_sequence [B,S,10]
    const int*   doy  = (const int*)  d_in[1];   // doy_sequence   [B,S]
    const float* W    = (const float*)d_in[2];   // W [256,10]
    const float* bias = (const float*)d_in[3];   // b [256]
    float*       out  = (float*)d_out;           // [B,S,512]

    const int nrows = in_sizes[1];               // B*S

    build_pe_kernel<<<MAX_LEN, 128>>>();
    bert_embed_kernel<<<NBLK, TPB>>>(x, doy, W, bias, out, nrows);
}

// round 3
// speedup vs baseline: 1.7986x; 1.2939x over previous
#include <cuda_runtime.h>
#include <cuda_bf16.h>
#include <math.h>

// BERTEmbedding: out[row, 0:256]   = x[row,0:10] @ W[256,10]^T + b
//                out[row, 256:512] = sinusoidal PE at pos = doy[row]
// rows = B*S = 131072; output 268 MB fp32 -> HBM-write-bound target.
//
// R3: tile R=8 rows per block iteration so the smem W read (10 LDS.128 per
// obs thread) amortizes over 8 rows (was per-row -> L1 crossbar bound at 72%).
// x/doy staged per tile into double-buffered smem (1 bar per tile).

#define MAX_LEN 366
#define D_HALF  256
#define TPB     128
#define R       8
#define NBLK    2048

__device__ float g_pe[MAX_LEN * D_HALF];  // [pos][col]

__global__ void build_pe_kernel() {
    const int pos = blockIdx.x;
    const int i   = threadIdx.x;                  // 0..127 -> cols 2i, 2i+1
    const float k = -9.210340371976184f / 256.0f; // -ln(10000)/D
    const float div = expf(k * (float)(2 * i));
    float s, c;
    sincosf((float)pos * div, &s, &c);
    g_pe[pos * D_HALF + 2 * i]     = s;
    g_pe[pos * D_HALF + 2 * i + 1] = c;
}

__global__ void __launch_bounds__(TPB) bert_embed_kernel(
    const float* __restrict__ x,      // [rows, 10]
    const int*   __restrict__ doy,    // [rows]
    const float* __restrict__ W,      // [256, 10] row-major
    const float* __restrict__ bias,   // [256]
    float*       __restrict__ out,    // [rows, 512]
    int nrows)
{
    __shared__ float s_wt[10 * D_HALF];   // W transposed: wt[f][c]
    __shared__ float s_b[D_HALF];
    __shared__ float s_x[2][R * 10];      // staged x tile (80 floats)
    __shared__ int   s_doy[2][R];

    const int t = threadIdx.x;

    // one-time fills
    for (int idx = t; idx < 10 * D_HALF; idx += TPB) {
        const int f = idx >> 8;
        const int c = idx & 255;
        s_wt[idx] = W[c * 10 + f];
    }
    for (int idx = t; idx < D_HALF; idx += TPB)
        s_b[idx] = bias[idx];

    const bool is_obs = (t < 64);
    const int  l      = t & 63;           // obs: f4-col index; PE: f4-col index

    const float4* wt4 = reinterpret_cast<const float4*>(s_wt);  // [10][64]
    const float4* pe4 = reinterpret_cast<const float4*>(g_pe);  // [366][64]
    float4*       o4  = reinterpret_cast<float4*>(out);         // [rows][128]

    const int ntiles = (nrows + R - 1) / R;

    // stage helper (inlined manually): threads 0..79 -> x floats, 96..103 -> doy
    int tile = blockIdx.x;
    {
        const int base = tile * R;
        if (t < R * 10) {
            int gi = base * 10 + t;
            s_x[0][t] = (gi < nrows * 10) ? x[gi] : 0.f;
        } else if (t >= 96 && t < 96 + R) {
            int r = t - 96;
            s_doy[0][r] = (base + r < nrows) ? doy[base + r] : 0;
        }
    }
    __syncthreads();

    float4 bv = make_float4(0.f, 0.f, 0.f, 0.f);
    if (is_obs) bv = reinterpret_cast<const float4*>(s_b)[l];

    int buf = 0;
    for (; tile < ntiles; tile += gridDim.x, buf ^= 1) {
        // stage next tile into the other buffer
        const int ntile = tile + gridDim.x;
        if (ntile < ntiles) {
            const int nb = ntile * R;
            if (t < R * 10) {
                int gi = nb * 10 + t;
                s_x[buf ^ 1][t] = (gi < nrows * 10) ? x[gi] : 0.f;
            } else if (t >= 96 && t < 96 + R) {
                int r = t - 96;
                s_doy[buf ^ 1][r] = (nb + r < nrows) ? doy[nb + r] : 0;
            }
        }

        const int rowbase = tile * R;
        if (is_obs) {
            float4 acc[R];
            #pragma unroll
            for (int r = 0; r < R; ++r) acc[r] = bv;

            #pragma unroll
            for (int f = 0; f < 10; ++f) {
                const float4 w = wt4[f * 64 + l];     // 1 LDS.128 per tile per f
                #pragma unroll
                for (int r = 0; r < R; ++r) {
                    const float xv = s_x[buf][r * 10 + f];  // broadcast LDS
                    acc[r].x = fmaf(xv, w.x, acc[r].x);
                    acc[r].y = fmaf(xv, w.y, acc[r].y);
                    acc[r].z = fmaf(xv, w.z, acc[r].z);
                    acc[r].w = fmaf(xv, w.w, acc[r].w);
                }
            }
            #pragma unroll
            for (int r = 0; r < R; ++r) {
                const int row = rowbase + r;
                if (row < nrows) o4[(size_t)row * 128 + l] = acc[r];
            }
        } else {
            #pragma unroll
            for (int r = 0; r < R; ++r) {
                const int row = rowbase + r;
                if (row < nrows) {
                    const int p = s_doy[buf][r];
                    o4[(size_t)row * 128 + 64 + l] = __ldg(pe4 + p * 64 + l);
                }
            }
        }
        __syncthreads();
    }
}

extern "C" void kernel_launch(void* const* d_in, const int* in_sizes, int n_in,
                              void* d_out, int out_size) {
    const float* x    = (const float*)d_in[0];   // input_sequence [B,S,10]
    const int*   doy  = (const int*)  d_in[1];   // doy_sequence   [B,S]
    const float* W    = (const float*)d_in[2];   // W [256,10]
    const float* bias = (const float*)d_in[3];   // b [256]
    float*       out  = (float*)d_out;           // [B,S,512]

    const int nrows = in_sizes[1];               // B*S

    build_pe_kernel<<<MAX_LEN, 128>>>();
    bert_embed_kernel<<<NBLK, TPB>>>(x, doy, W, bias, out, nrows);
}

// round 7
// speedup vs baseline: 2.1103x; 1.1733x over previous
#include <cuda_runtime.h>
#include <cuda_bf16.h>
#include <math.h>

// BERTEmbedding: out[row, 0:256]   = x[row,0:10] @ W[256,10]^T + b
//                out[row, 256:512] = sinusoidal PE at pos = doy[row]
// rows = B*S = 131072; output 268 MB fp32 -> HBM-write-bound target.
//
// R4: W lives in 40 registers per obs thread (loop-invariant, loaded once) and
// rows are processed one-at-a-time (acc = 4 regs) instead of an acc[8] tile
// (R3 hit 88 regs -> 5 blocks/SM -> occ 28.6%, DRAM 44%). launch_bounds(128,8)
// pins 8 blocks/SM. x/doy staged per R=8 tile in double-buffered smem.

#define MAX_LEN 366
#define D_HALF  256
#define TPB     128
#define R       8
#define NBLK    2048

__device__ float g_pe[MAX_LEN * D_HALF];  // [pos][col]

__global__ void build_pe_kernel() {
    const int pos = blockIdx.x;
    const int i   = threadIdx.x;                  // 0..127 -> cols 2i, 2i+1
    const float k = -9.210340371976184f / 256.0f; // -ln(10000)/D
    const float div = expf(k * (float)(2 * i));
    float s, c;
    sincosf((float)pos * div, &s, &c);
    g_pe[pos * D_HALF + 2 * i]     = s;
    g_pe[pos * D_HALF + 2 * i + 1] = c;
}

__global__ void __launch_bounds__(TPB, 8) bert_embed_kernel(
    const float* __restrict__ x,      // [rows, 10]
    const int*   __restrict__ doy,    // [rows]
    const float* __restrict__ W,      // [256, 10] row-major
    const float* __restrict__ bias,   // [256]
    float*       __restrict__ out,    // [rows, 512]
    int nrows)
{
    __shared__ float s_x[2][R * 10];      // staged x tile (80 floats/buf)
    __shared__ int   s_doy[2][R];

    const int  t      = threadIdx.x;
    const bool is_obs = (t < 64);
    const int  l      = t & 63;

    // ---- loop-invariant W/bias in registers (obs threads only) ----
    // thread l owns output cols 4l..4l+3; w[f] = (W[4l+0..3][f]) as float4
    float4 wv[10];
    float4 bv = make_float4(0.f, 0.f, 0.f, 0.f);
    if (is_obs) {
        const int c0 = l * 4;
        #pragma unroll
        for (int f = 0; f < 10; ++f)
            wv[f] = make_float4(W[(c0 + 0) * 10 + f], W[(c0 + 1) * 10 + f],
                                W[(c0 + 2) * 10 + f], W[(c0 + 3) * 10 + f]);
        bv = make_float4(bias[c0], bias[c0 + 1], bias[c0 + 2], bias[c0 + 3]);
    }

    const float4* pe4 = reinterpret_cast<const float4*>(g_pe);  // [366][64]
    float4*       o4  = reinterpret_cast<float4*>(out);         // [rows][128]

    const int ntiles = (nrows + R - 1) / R;

    // stage first tile
    int tile = blockIdx.x;
    {
        const int base = tile * R;
        if (t < R * 10) {
            const int gi = base * 10 + t;
            s_x[0][t] = (gi < nrows * 10) ? x[gi] : 0.f;
        } else if (t >= 96 && t < 96 + R) {
            const int r = t - 96;
            s_doy[0][r] = (base + r < nrows) ? doy[base + r] : 0;
        }
    }
    __syncthreads();

    int buf = 0;
    for (; tile < ntiles; tile += gridDim.x, buf ^= 1) {
        // prefetch next tile into other buffer
        const int ntile = tile + gridDim.x;
        if (ntile < ntiles) {
            const int nb = ntile * R;
            if (t < R * 10) {
                const int gi = nb * 10 + t;
                s_x[buf ^ 1][t] = (gi < nrows * 10) ? x[gi] : 0.f;
            } else if (t >= 96 && t < 96 + R) {
                const int r = t - 96;
                s_doy[buf ^ 1][r] = (nb + r < nrows) ? doy[nb + r] : 0;
            }
        }

        const int rowbase = tile * R;
        if (is_obs) {
            #pragma unroll
            for (int r = 0; r < R; ++r) {
                const int row = rowbase + r;
                if (row >= nrows) break;
                float4 acc = bv;
                #pragma unroll
                for (int f = 0; f < 10; ++f) {
                    const float xv = s_x[buf][r * 10 + f];   // broadcast LDS
                    acc.x = fmaf(xv, wv[f].x, acc.x);
                    acc.y = fmaf(xv, wv[f].y, acc.y);
                    acc.z = fmaf(xv, wv[f].z, acc.z);
                    acc.w = fmaf(xv, wv[f].w, acc.w);
                }
                o4[(size_t)row * 128 + l] = acc;
            }
        } else {
            #pragma unroll
            for (int r = 0; r < R; ++r) {
                const int row = rowbase + r;
                if (row >= nrows) break;
                const int p = s_doy[buf][r];
                o4[(size_t)row * 128 + 64 + l] = __ldg(pe4 + p * 64 + l);
            }
        }
        __syncthreads();
    }
}

extern "C" void kernel_launch(void* const* d_in, const int* in_sizes, int n_in,
                              void* d_out, int out_size) {
    const float* x    = (const float*)d_in[0];   // input_sequence [B,S,10]
    const int*   doy  = (const int*)  d_in[1];   // doy_sequence   [B,S]
    const float* W    = (const float*)d_in[2];   // W [256,10]
    const float* bias = (const float*)d_in[3];   // b [256]
    float*       out  = (float*)d_out;           // [B,S,512]

    const int nrows = in_sizes[1];               // B*S

    build_pe_kernel<<<MAX_LEN, 128>>>();
    bert_embed_kernel<<<NBLK, TPB>>>(x, doy, W, bias, out, nrows);
}

// round 8
// speedup vs baseline: 2.1835x; 1.0347x over previous
#include <cuda_runtime.h>
#include <cuda_bf16.h>
#include <math.h>

// BERTEmbedding: out[row, 0:256]   = x[row,0:10] @ W[256,10]^T + b
//                out[row, 256:512] = sinusoidal PE at pos = doy[row]
// rows = B*S = 131072; output 268 MB fp32 -> HBM-write-bound target.
//
// R8: PE computed INLINE with a fast accurate sincos (FMA Cody-Waite 2-term
// reduction + deg-9/8 polys, abs err ~5e-8 for |ang|<=365). Kills the 5.4us
// build_pe prologue + graph gap and the 134 MB of PE table gathers from L2.
// Obs half unchanged: W in 40 loop-invariant regs, 8 blocks/SM.

#define MAX_LEN 366
#define D_HALF  256
#define TPB     128
#define R       8
#define NBLK    2048

// sin/cos for a in [0, 366]: n = rint(a*2/pi), r = a - n*pi/2 (2-term FMA
// reduction, exact-cancellation safe), then odd/even polynomials + quadrant.
__device__ __forceinline__ void fast_sincos(float a, float& s, float& c) {
    const float nf = rintf(a * 0.636619772367581343f);   // 2/pi
    const int   q  = (int)nf;
    float r = fmaf(nf, -1.57079637050628662109375f, a);  // RN(pi/2)
    r       = fmaf(nf,  4.37113900018630027771e-8f, r);  // -(pi/2 - C1)
    const float r2 = r * r;

    float ps = 2.75573192e-6f;                  // sin poly (odd, deg 9)
    ps = fmaf(ps, r2, -1.98412698e-4f);
    ps = fmaf(ps, r2,  8.33333333e-3f);
    ps = fmaf(ps, r2, -1.66666667e-1f);
    const float sr = fmaf(ps * r2, r, r);

    float pc = 2.48015873e-5f;                  // cos poly (even, deg 8)
    pc = fmaf(pc, r2, -1.38888889e-3f);
    pc = fmaf(pc, r2,  4.16666667e-2f);
    pc = fmaf(pc, r2, -0.5f);
    const float cr = fmaf(pc, r2, 1.0f);

    const bool swap = (q & 1);
    float so = swap ? cr : sr;
    float co = swap ? sr : cr;
    if (q & 2)       so = -so;                  // sin neg in quadrants 2,3
    if ((q + 1) & 2) co = -co;                  // cos neg in quadrants 1,2
    s = so;
    c = co;
}

__global__ void __launch_bounds__(TPB, 8) bert_embed_kernel(
    const float* __restrict__ x,      // [rows, 10]
    const int*   __restrict__ doy,    // [rows]
    const float* __restrict__ W,      // [256, 10] row-major
    const float* __restrict__ bias,   // [256]
    float*       __restrict__ out,    // [rows, 512]
    int nrows)
{
    __shared__ float s_x[2][R * 10];      // staged x tile (80 floats/buf)
    __shared__ int   s_doy[2][R];

    const int  t      = threadIdx.x;
    const bool is_obs = (t < 64);
    const int  l      = t & 63;

    // ---- loop-invariant per-thread constants ----
    // obs thread l: output cols 4l..4l+3 -> 10x float4 of W + bias float4.
    // PE thread l:  output cols 256+4l..: sin/cos at freqs i0=2l, i1=2l+1.
    float4 wv[10];
    float4 bv   = make_float4(0.f, 0.f, 0.f, 0.f);
    float  div0 = 0.f, div1 = 0.f;
    if (is_obs) {
        const int c0 = l * 4;
        #pragma unroll
        for (int f = 0; f < 10; ++f)
            wv[f] = make_float4(W[(c0 + 0) * 10 + f], W[(c0 + 1) * 10 + f],
                                W[(c0 + 2) * 10 + f], W[(c0 + 3) * 10 + f]);
        bv = make_float4(bias[c0], bias[c0 + 1], bias[c0 + 2], bias[c0 + 3]);
    } else {
        const float k = -9.210340371976184f / 256.0f;  // -ln(10000)/D
        div0 = expf(k * (float)(4 * l));               // exp(k*2*i0), i0=2l
        div1 = expf(k * (float)(4 * l + 2));           // i1=2l+1
    }

    float4* o4 = reinterpret_cast<float4*>(out);       // [rows][128]

    const int ntiles = (nrows + R - 1) / R;

    // stage first tile
    int tile = blockIdx.x;
    {
        const int base = tile * R;
        if (t < R * 10) {
            const int gi = base * 10 + t;
            s_x[0][t] = (gi < nrows * 10) ? x[gi] : 0.f;
        } else if (t >= 96 && t < 96 + R) {
            const int r = t - 96;
            s_doy[0][r] = (base + r < nrows) ? doy[base + r] : 0;
        }
    }
    __syncthreads();

    int buf = 0;
    for (; tile < ntiles; tile += gridDim.x, buf ^= 1) {
        // prefetch next tile into other buffer
        const int ntile = tile + gridDim.x;
        if (ntile < ntiles) {
            const int nb = ntile * R;
            if (t < R * 10) {
                const int gi = nb * 10 + t;
                s_x[buf ^ 1][t] = (gi < nrows * 10) ? x[gi] : 0.f;
            } else if (t >= 96 && t < 96 + R) {
                const int r = t - 96;
                s_doy[buf ^ 1][r] = (nb + r < nrows) ? doy[nb + r] : 0;
            }
        }

        const int rowbase = tile * R;
        if (is_obs) {
            #pragma unroll
            for (int r = 0; r < R; ++r) {
                const int row = rowbase + r;
                if (row >= nrows) break;
                float4 acc = bv;
                #pragma unroll
                for (int f = 0; f < 10; ++f) {
                    const float xv = s_x[buf][r * 10 + f];   // broadcast LDS
                    acc.x = fmaf(xv, wv[f].x, acc.x);
                    acc.y = fmaf(xv, wv[f].y, acc.y);
                    acc.z = fmaf(xv, wv[f].z, acc.z);
                    acc.w = fmaf(xv, wv[f].w, acc.w);
                }
                o4[(size_t)row * 128 + l] = acc;
            }
        } else {
            #pragma unroll
            for (int r = 0; r < R; ++r) {
                const int row = rowbase + r;
                if (row >= nrows) break;
                const float pos = (float)s_doy[buf][r];
                float4 v;
                fast_sincos(pos * div0, v.x, v.y);
                fast_sincos(pos * div1, v.z, v.w);
                o4[(size_t)row * 128 + 64 + l] = v;
            }
        }
        __syncthreads();
    }
}

extern "C" void kernel_launch(void* const* d_in, const int* in_sizes, int n_in,
                              void* d_out, int out_size) {
    const float* x    = (const float*)d_in[0];   // input_sequence [B,S,10]
    const int*   doy  = (const int*)  d_in[1];   // doy_sequence   [B,S]
    const float* W    = (const float*)d_in[2];   // W [256,10]
    const float* bias = (const float*)d_in[3];   // b [256]
    float*       out  = (float*)d_out;           // [B,S,512]

    const int nrows = in_sizes[1];               // B*S

    bert_embed_kernel<<<NBLK, TPB>>>(x, doy, W, bias, out, nrows);
}

// round 10
// speedup vs baseline: 2.2261x; 1.0195x over previous
#include <cuda_runtime.h>
#include <cuda_bf16.h>
#include <math.h>

// BERTEmbedding: out[row, 0:256]   = x[row,0:10] @ W[256,10]^T + b
//                out[row, 256:512] = sinusoidal PE at pos = doy[row]
// rows = B*S = 131072; output 268 MB fp32 -> HBM-write-bound target.
//
// R9: PE sincos moved from a ~36-op FFMA polynomial (R8: fma 31%, alu 27%,
// issue 58% -> starved the store stream) to the MUFU hardware path
// (__sincosf = RRO + MUFU.SIN/COS, ~4-6 warp-ops, ~8us of MUFU time chip-wide,
// hidden under the HBM store envelope). |ang| <= 366 -> RRO reduction abs err
// ~1e-5 << 1e-3 gate. Obs half unchanged: W in 40 loop-invariant regs,
// 8 blocks/SM, double-buffered x/doy staging.

#define MAX_LEN 366
#define D_HALF  256
#define TPB     128
#define R       8
#define NBLK    2048

__global__ void __launch_bounds__(TPB, 8) bert_embed_kernel(
    const float* __restrict__ x,      // [rows, 10]
    const int*   __restrict__ doy,    // [rows]
    const float* __restrict__ W,      // [256, 10] row-major
    const float* __restrict__ bias,   // [256]
    float*       __restrict__ out,    // [rows, 512]
    int nrows)
{
    __shared__ float s_x[2][R * 10];      // staged x tile (80 floats/buf)
    __shared__ int   s_doy[2][R];

    const int  t      = threadIdx.x;
    const bool is_obs = (t < 64);
    const int  l      = t & 63;

    // ---- loop-invariant per-thread constants ----
    // obs thread l: output cols 4l..4l+3 -> 10x float4 of W + bias float4.
    // PE thread l:  output cols 256+4l..: sin/cos at freqs i0=2l, i1=2l+1.
    float4 wv[10];
    float4 bv   = make_float4(0.f, 0.f, 0.f, 0.f);
    float  div0 = 0.f, div1 = 0.f;
    if (is_obs) {
        const int c0 = l * 4;
        #pragma unroll
        for (int f = 0; f < 10; ++f)
            wv[f] = make_float4(W[(c0 + 0) * 10 + f], W[(c0 + 1) * 10 + f],
                                W[(c0 + 2) * 10 + f], W[(c0 + 3) * 10 + f]);
        bv = make_float4(bias[c0], bias[c0 + 1], bias[c0 + 2], bias[c0 + 3]);
    } else {
        const float k = -9.210340371976184f / 256.0f;  // -ln(10000)/D
        div0 = expf(k * (float)(4 * l));               // exp(k*2*i0), i0=2l
        div1 = expf(k * (float)(4 * l + 2));           // i1=2l+1
    }

    float4* o4 = reinterpret_cast<float4*>(out);       // [rows][128]

    const int ntiles = (nrows + R - 1) / R;

    // stage first tile
    int tile = blockIdx.x;
    {
        const int base = tile * R;
        if (t < R * 10) {
            const int gi = base * 10 + t;
            s_x[0][t] = (gi < nrows * 10) ? x[gi] : 0.f;
        } else if (t >= 96 && t < 96 + R) {
            const int r = t - 96;
            s_doy[0][r] = (base + r < nrows) ? doy[base + r] : 0;
        }
    }
    __syncthreads();

    int buf = 0;
    for (; tile < ntiles; tile += gridDim.x, buf ^= 1) {
        // prefetch next tile into other buffer
        const int ntile = tile + gridDim.x;
        if (ntile < ntiles) {
            const int nb = ntile * R;
            if (t < R * 10) {
                const int gi = nb * 10 + t;
                s_x[buf ^ 1][t] = (gi < nrows * 10) ? x[gi] : 0.f;
            } else if (t >= 96 && t < 96 + R) {
                const int r = t - 96;
                s_doy[buf ^ 1][r] = (nb + r < nrows) ? doy[nb + r] : 0;
            }
        }

        const int rowbase = tile * R;
        if (is_obs) {
            #pragma unroll
            for (int r = 0; r < R; ++r) {
                const int row = rowbase + r;
                if (row >= nrows) break;
                float4 acc = bv;
                #pragma unroll
                for (int f = 0; f < 10; ++f) {
                    const float xv = s_x[buf][r * 10 + f];   // broadcast LDS
                    acc.x = fmaf(xv, wv[f].x, acc.x);
                    acc.y = fmaf(xv, wv[f].y, acc.y);
                    acc.z = fmaf(xv, wv[f].z, acc.z);
                    acc.w = fmaf(xv, wv[f].w, acc.w);
                }
                o4[(size_t)row * 128 + l] = acc;
            }
        } else {
            #pragma unroll
            for (int r = 0; r < R; ++r) {
                const int row = rowbase + r;
                if (row >= nrows) break;
                const float pos = (float)s_doy[buf][r];
                float4 v;
                __sincosf(pos * div0, &v.x, &v.y);   // RRO + MUFU pair
                __sincosf(pos * div1, &v.z, &v.w);
                o4[(size_t)row * 128 + 64 + l] = v;
            }
        }
        __syncthreads();
    }
}

extern "C" void kernel_launch(void* const* d_in, const int* in_sizes, int n_in,
                              void* d_out, int out_size) {
    const float* x    = (const float*)d_in[0];   // input_sequence [B,S,10]
    const int*   doy  = (const int*)  d_in[1];   // doy_sequence   [B,S]
    const float* W    = (const float*)d_in[2];   // W [256,10]
    const float* bias = (const float*)d_in[3];   // b [256]
    float*       out  = (float*)d_out;           // [B,S,512]

    const int nrows = in_sizes[1];               // B*S

    bert_embed_kernel<<<NBLK, TPB>>>(x, doy, W, bias, out, nrows);
}

// round 11
// speedup vs baseline: 2.4176x; 1.0860x over previous
#include <cuda_runtime.h>
#include <cuda_bf16.h>
#include <math.h>

// BERTEmbedding: out[row, 0:256]   = x[row,0:10] @ W[256,10]^T + b
//                out[row, 256:512] = sinusoidal PE at pos = doy[row]
// rows = B*S = 131072; output 268 MB fp32 -> HBM-write-bound target.
//
// R11: occupancy was reg-capped (40-reg W cache -> 64 regs -> 50% max occ,
// DRAM stuck at 56%). Now 2 output cols per obs thread (W = 20 regs),
// TPB=256: t0..127 obs (float2 stores), t128..255 PE (one MUFU sincos pair
// per row). launch_bounds(256,6) -> 48 warps/SM (75%). Grid = 888 = exactly
// one persistent wave (6 blocks x 148 SMs), grid-stride over row tiles.

#define TPB   256
#define R     8
#define NBLK  888   // 148 SMs * 6 resident blocks

__global__ void __launch_bounds__(TPB, 6) bert_embed_kernel(
    const float* __restrict__ x,      // [rows, 10]
    const int*   __restrict__ doy,    // [rows]
    const float* __restrict__ W,      // [256, 10] row-major
    const float* __restrict__ bias,   // [256]
    float*       __restrict__ out,    // [rows, 512]
    int nrows)
{
    __shared__ float s_x[2][R * 10];      // staged x tile (80 floats/buf)
    __shared__ int   s_doy[2][R];

    const int  t      = threadIdx.x;
    const bool is_obs = (t < 128);

    // ---- loop-invariant per-thread constants ----
    // obs thread t: output cols 2t, 2t+1 -> 10x float2 of W + bias float2.
    // PE thread (t-128)=i: cols 256+2i (sin), 257+2i (cos); freq div(i).
    float2 wv[10];
    float2 bv  = make_float2(0.f, 0.f);
    float  div = 0.f;
    if (is_obs) {
        const int c0 = t * 2;
        #pragma unroll
        for (int f = 0; f < 10; ++f)
            wv[f] = make_float2(W[c0 * 10 + f], W[(c0 + 1) * 10 + f]);
        bv = make_float2(bias[c0], bias[c0 + 1]);
    } else {
        const int   i = t - 128;
        const float k = -9.210340371976184f / 256.0f;  // -ln(10000)/D
        div = expf(k * (float)(2 * i));
    }

    float2* o2 = reinterpret_cast<float2*>(out);       // [rows][256]

    const int ntiles = (nrows + R - 1) / R;

    // stage first tile
    int tile = blockIdx.x;
    {
        const int base = tile * R;
        if (t < R * 10) {
            const int gi = base * 10 + t;
            s_x[0][t] = (gi < nrows * 10) ? x[gi] : 0.f;
        } else if (t >= 96 && t < 96 + R) {
            const int r = t - 96;
            s_doy[0][r] = (base + r < nrows) ? doy[base + r] : 0;
        }
    }
    __syncthreads();

    int buf = 0;
    for (; tile < ntiles; tile += gridDim.x, buf ^= 1) {
        // prefetch next tile into the other buffer
        const int ntile = tile + gridDim.x;
        if (ntile < ntiles) {
            const int nb = ntile * R;
            if (t < R * 10) {
                const int gi = nb * 10 + t;
                s_x[buf ^ 1][t] = (gi < nrows * 10) ? x[gi] : 0.f;
            } else if (t >= 96 && t < 96 + R) {
                const int r = t - 96;
                s_doy[buf ^ 1][r] = (nb + r < nrows) ? doy[nb + r] : 0;
            }
        }

        const int rowbase = tile * R;
        if (is_obs) {
            #pragma unroll
            for (int r = 0; r < R; ++r) {
                const int row = rowbase + r;
                if (row >= nrows) break;
                float2 acc = bv;
                #pragma unroll
                for (int f = 0; f < 10; ++f) {
                    const float xv = s_x[buf][r * 10 + f];   // broadcast LDS
                    acc.x = fmaf(xv, wv[f].x, acc.x);
                    acc.y = fmaf(xv, wv[f].y, acc.y);
                }
                o2[(size_t)row * 256 + t] = acc;            // cols 2t,2t+1
            }
        } else {
            const int i = t - 128;
            #pragma unroll
            for (int r = 0; r < R; ++r) {
                const int row = rowbase + r;
                if (row >= nrows) break;
                const float pos = (float)s_doy[buf][r];
                float2 v;
                __sincosf(pos * div, &v.x, &v.y);           // MUFU pair
                o2[(size_t)row * 256 + 128 + i] = v;        // cols 256+2i,+1
            }
        }
        __syncthreads();
    }
}

extern "C" void kernel_launch(void* const* d_in, const int* in_sizes, int n_in,
                              void* d_out, int out_size) {
    const float* x    = (const float*)d_in[0];   // input_sequence [B,S,10]
    const int*   doy  = (const int*)  d_in[1];   // doy_sequence   [B,S]
    const float* W    = (const float*)d_in[2];   // W [256,10]
    const float* bias = (const float*)d_in[3];   // b [256]
    float*       out  = (float*)d_out;           // [B,S,512]

    const int nrows = in_sizes[1];               // B*S

    bert_embed_kernel<<<NBLK, TPB>>>(x, doy, W, bias, out, nrows);
}